// round 5
// baseline (speedup 1.0000x reference)
#include <cuda_runtime.h>

#define NQ     10
#define NL     4
#define WPB    4
#define BLOCK  (32 * WPB)

typedef unsigned long long u64;

// Packed gate coefficients: per gate 8 u64:
// {P00,Q00,P10,Q10,P01,Q01,P11,Q11}, P(M)=(re,im), Q(M)=(-im,re)
__device__   u64 gPackedBuf[NL * NQ * 8];
__constant__ u64 cG[NL * NQ * 8];

// ============================================================
// Compile-time GF(2) frame tables. The CNOT ring sigma is linear
// on index bits; gates in layer l act in frame sigma^{-l}.
// ============================================================
__host__ __device__ constexpr int parc(int v) {
    int c = 0;
    for (int b = 0; b < NQ; ++b) c ^= (v >> b) & 1;
    return c;
}

constexpr int sigma1(int j) {   // identical to R1's verified cnot_src
    int s = j;
    for (int q = 9; q >= 0; --q) {
        int pc = 9 - q;
        int pt = 9 - ((q + 1) % 10);
        s ^= ((s >> pc) & 1) << pt;
    }
    return s;
}

struct MaskTab {
    int m[NL][NQ];        // physical xor-mask of gate (layer, bit-position p)
    int sel[NL + 1][NQ];  // role selector rows; sel[NL] drives readout signs
};

constexpr MaskTab build_masks() {
    MaskTab t{};
    int perm[1024] = {};
    for (int j = 0; j < 1024; ++j) perm[j] = j;
    int inv[1024] = {};
    for (int l = 0; l <= NL; ++l) {
        if (l < NL)
            for (int p = 0; p < NQ; ++p) t.m[l][p] = perm[1 << p];
        for (int j = 0; j < 1024; ++j) inv[perm[j]] = j;
        for (int p = 0; p < NQ; ++p) {
            int s = 0;
            for (int b = 0; b < NQ; ++b) s |= ((inv[1 << b] >> p) & 1) << b;
            t.sel[l][p] = s;
        }
        if (l < NL) {
            int nxt[1024] = {};
            for (int j = 0; j < 1024; ++j) nxt[j] = perm[sigma1(j)];
            for (int j = 0; j < 1024; ++j) perm[j] = nxt[j];
        }
    }
    return t;
}
constexpr MaskTab MT = build_masks();

// ============================================================
// Packed f32x2 helpers
// ============================================================
__device__ __forceinline__ u64 pk2(float a, float b) {
    u64 r; asm("mov.b64 %0, {%1, %2};" : "=l"(r) : "f"(a), "f"(b)); return r;
}
__device__ __forceinline__ void upk(u64 v, float& a, float& b) {
    asm("mov.b64 {%0, %1}, %2;" : "=f"(a), "=f"(b) : "l"(v));
}
__device__ __forceinline__ u64 fma2(u64 a, u64 b, u64 c) {
    u64 d; asm("fma.rn.f32x2 %0, %1, %2, %3;" : "=l"(d) : "l"(a), "l"(b), "l"(c)); return d;
}
__device__ __forceinline__ u64 mul2(u64 a, u64 b) {
    u64 d; asm("mul.rn.f32x2 %0, %1, %2;" : "=l"(d) : "l"(a), "l"(b)); return d;
}

// ============================================================
// Setup: fuse Rx*Ry*Rz per (layer,qubit)
// ============================================================
struct c2 { float x, y; };
__device__ __forceinline__ c2 cmulh(c2 a, c2 b) { return { a.x*b.x - a.y*b.y, a.x*b.y + a.y*b.x }; }
__device__ __forceinline__ c2 caddh(c2 a, c2 b) { return { a.x + b.x, a.y + b.y }; }

__global__ void tq_setup_kernel(const float* __restrict__ theta) {
    int t = threadIdx.x;
    if (t >= NL * NQ) return;
    float t0 = theta[t*3+0], t1 = theta[t*3+1], t2 = theta[t*3+2];
    float cx = cosf(0.5f*t0), sx = sinf(0.5f*t0);
    float cy = cosf(0.5f*t1), sy = sinf(0.5f*t1);
    float cz = cosf(0.5f*t2), sz = sinf(0.5f*t2);

    c2 x00{cx,0.f}, x01{0.f,-sx}, x10{0.f,-sx}, x11{cx,0.f};
    c2 y00{cy,0.f}, y01{-sy,0.f}, y10{sy,0.f},  y11{cy,0.f};

    c2 A00 = caddh(cmulh(x00,y00), cmulh(x01,y10));
    c2 A01 = caddh(cmulh(x00,y01), cmulh(x01,y11));
    c2 A10 = caddh(cmulh(x10,y00), cmulh(x11,y10));
    c2 A11 = caddh(cmulh(x10,y01), cmulh(x11,y11));

    c2 e0{cz,-sz}, e1{cz,sz};
    c2 M00 = cmulh(A00,e0), M01 = cmulh(A01,e1);
    c2 M10 = cmulh(A10,e0), M11 = cmulh(A11,e1);

    u64* o = &gPackedBuf[t*8];
    o[0] = pk2(M00.x, M00.y);  o[1] = pk2(-M00.y, M00.x);
    o[2] = pk2(M10.x, M10.y);  o[3] = pk2(-M10.y, M10.x);
    o[4] = pk2(M01.x, M01.y);  o[5] = pk2(-M01.y, M01.x);
    o[6] = pk2(M11.x, M11.y);  o[7] = pk2(-M11.y, M11.x);
}

// ============================================================
// One gate, layer L, virtual bit-position P, applied in frame sigma^{-L}.
// Amp layout: phys index i = (k<<5)|lane, k = register index.
// role(i) = parc(i & sel);  partner(i) = i ^ m.
// role0: n = me*M00 + partner*M10 ; role1: n = me*M11 + partner*M01
// ============================================================
template<int L, int P>
__device__ __forceinline__ void apply_gate(float2* st, int lane) {
    constexpr int m   = MT.m[L][P];
    constexpr int sl  = MT.sel[L][P];
    static_assert(parc(m & sl) == 1, "pair must flip role");
    constexpr int mreg = (m >> 5) & 31, mlane = m & 31;
    constexpr int selreg = (sl >> 5) & 31, sellane = sl & 31;
    constexpr int g8 = (L * NQ + (9 - P)) * 8;

    u64 A0 = cG[g8+0], Q0 = cG[g8+1], B0 = cG[g8+2], S0 = cG[g8+3];
    u64 A1 = cG[g8+6], Q1 = cG[g8+7], B1 = cG[g8+4], S1 = cG[g8+5];
    if constexpr (sellane != 0) {
        const bool lp = (__popc(lane & sellane) & 1) != 0;
        u64 t;
        t = A0; A0 = lp ? A1 : A0; A1 = lp ? t : A1;
        t = Q0; Q0 = lp ? Q1 : Q0; Q1 = lp ? t : Q1;
        t = B0; B0 = lp ? B1 : B0; B1 = lp ? t : B1;
        t = S0; S0 = lp ? S1 : S0; S1 = lp ? t : S1;
    }

    if constexpr (mreg == 0) {
#pragma unroll
        for (int k = 0; k < 32; ++k) {
            float px = __shfl_xor_sync(0xffffffffu, st[k].x, mlane);
            float py = __shfl_xor_sync(0xffffffffu, st[k].y, mlane);
            const bool r = parc(k & selreg) != 0;   // constant-folds after unroll
            u64 n = fma2(pk2(py, py), r ? S1 : S0,
                    fma2(pk2(px, px), r ? B1 : B0,
                    fma2(pk2(st[k].y, st[k].y), r ? Q1 : Q0,
                    mul2(pk2(st[k].x, st[k].x), r ? A1 : A0))));
            upk(n, st[k].x, st[k].y);
        }
    } else {
        constexpr int hb = mreg & (-mreg);
#pragma unroll
        for (int k = 0; k < 32; ++k) {
            if ((k & hb) == 0) {
                const int k2 = k ^ mreg;
                float ax = st[k].x,  ay = st[k].y;
                float bx = st[k2].x, by = st[k2].y;
                float pax = bx, pay = by, pbx = ax, pby = ay;
                if constexpr (mlane != 0) {
                    pax = __shfl_xor_sync(0xffffffffu, bx, mlane);
                    pay = __shfl_xor_sync(0xffffffffu, by, mlane);
                    pbx = __shfl_xor_sync(0xffffffffu, ax, mlane);
                    pby = __shfl_xor_sync(0xffffffffu, ay, mlane);
                }
                const bool ra = parc(k  & selreg) != 0;
                const bool rb = parc(k2 & selreg) != 0;
                u64 na = fma2(pk2(pay, pay), ra ? S1 : S0,
                         fma2(pk2(pax, pax), ra ? B1 : B0,
                         fma2(pk2(ay, ay),   ra ? Q1 : Q0,
                         mul2(pk2(ax, ax),   ra ? A1 : A0))));
                u64 nb = fma2(pk2(pby, pby), rb ? S1 : S0,
                         fma2(pk2(pbx, pbx), rb ? B1 : B0,
                         fma2(pk2(by, by),   rb ? Q1 : Q0,
                         mul2(pk2(bx, bx),   rb ? A1 : A0))));
                upk(na, st[k].x,  st[k].y);
                upk(nb, st[k2].x, st[k2].y);
            }
        }
    }
}

template<int L>
__device__ __forceinline__ void layer(float2* st, int lane) {
    apply_gate<L, 9>(st, lane);   // q = 0
    apply_gate<L, 8>(st, lane);
    apply_gate<L, 7>(st, lane);
    apply_gate<L, 6>(st, lane);
    apply_gate<L, 5>(st, lane);
    apply_gate<L, 4>(st, lane);
    apply_gate<L, 3>(st, lane);
    apply_gate<L, 2>(st, lane);
    apply_gate<L, 1>(st, lane);
    apply_gate<L, 0>(st, lane);   // q = 9
    // CNOT ring: free (absorbed into the next frame)
}

// ============================================================
// Readout for qubit Q in frame sigma^{-NL} — all MT accesses are
// constant expressions (template parameter), no device MT storage.
// ============================================================
template<int Q>
__device__ __forceinline__ float readout_one(const float* p, int lane) {
    constexpr int sel = MT.sel[NL][9 - Q];
    constexpr int sr  = (sel >> 5) & 31;
    constexpr int slq = sel & 31;
    float a = 0.f;
#pragma unroll
    for (int k = 0; k < 32; ++k)
        a += parc(k & sr) ? -p[k] : p[k];
    if constexpr (slq != 0) {
        if (__popc(lane & slq) & 1) a = -a;
    }
#pragma unroll
    for (int off = 16; off; off >>= 1)
        a += __shfl_xor_sync(0xffffffffu, a, off);
    return a;
}

// ============================================================
// Main kernel: one warp per batch element, state in registers
// ============================================================
__global__ __launch_bounds__(BLOCK)
void tq_main_kernel(const float* __restrict__ x,
                    const float* __restrict__ W,
                    const float* __restrict__ bias,
                    float* __restrict__ out) {
    const int lane = threadIdx.x & 31;
    const int b    = blockIdx.x * WPB + (threadIdx.x >> 5);

    float cq[NQ], sq[NQ];
    {
        float x0 = x[b*3+0], x1 = x[b*3+1], x2 = x[b*3+2];
#pragma unroll
        for (int q = 0; q < NQ; ++q) {
            float z = fmaf(x0, W[q*3+0], fmaf(x1, W[q*3+1], fmaf(x2, W[q*3+2], bias[q])));
            float e = 3.14159265358979323846f * tanhf(z);
            sincosf(0.5f * e, &sq[q], &cq[q]);
        }
    }

    // product-state init (frame 0 = identity)
    float2 st[32];
    {
        float fl = 1.f;
#pragma unroll
        for (int p = 0; p < 5; ++p)
            fl *= ((lane >> p) & 1) ? -sq[9 - p] : cq[9 - p];
        st[0].x = fl;
#pragma unroll
        for (int bit = 0; bit < 5; ++bit) {
            int q = 4 - bit;
#pragma unroll
            for (int k = (1 << bit) - 1; k >= 0; --k) {
                st[k | (1 << bit)].x = st[k].x * (-sq[q]);
                st[k].x              = st[k].x * cq[q];
            }
        }
#pragma unroll
        for (int k = 0; k < 32; ++k) st[k].y = 0.f;
    }

    layer<0>(st, lane);
    layer<1>(st, lane);
    layer<2>(st, lane);
    layer<3>(st, lane);

    // probabilities, then frame-rotated Z expectations
    float p[32];
#pragma unroll
    for (int k = 0; k < 32; ++k)
        p[k] = fmaf(st[k].x, st[k].x, st[k].y * st[k].y);

    float e[NQ];
    e[0] = readout_one<0>(p, lane);
    e[1] = readout_one<1>(p, lane);
    e[2] = readout_one<2>(p, lane);
    e[3] = readout_one<3>(p, lane);
    e[4] = readout_one<4>(p, lane);
    e[5] = readout_one<5>(p, lane);
    e[6] = readout_one<6>(p, lane);
    e[7] = readout_one<7>(p, lane);
    e[8] = readout_one<8>(p, lane);
    e[9] = readout_one<9>(p, lane);

    if (lane == 0) {
#pragma unroll
        for (int q = 0; q < NQ; ++q) out[b * NQ + q] = e[q];
    }
}

extern "C" void kernel_launch(void* const* d_in, const int* in_sizes, int n_in,
                              void* d_out, int out_size) {
    const float* x     = (const float*)d_in[0];   // [16384, 3]
    const float* enc_W = (const float*)d_in[1];   // [10, 3]
    const float* enc_b = (const float*)d_in[2];   // [10]
    const float* theta = (const float*)d_in[3];   // [4, 10, 3]
    float* out = (float*)d_out;                   // [16384, 10]

    int batch = in_sizes[0] / 3;

    tq_setup_kernel<<<1, 64>>>(theta);

    void* src = nullptr;
    cudaGetSymbolAddress(&src, gPackedBuf);
    cudaMemcpyToSymbolAsync(cG, src, sizeof(u64) * NL * NQ * 8, 0,
                            cudaMemcpyDeviceToDevice, 0);

    tq_main_kernel<<<batch / WPB, BLOCK>>>(x, enc_W, enc_b, out);
}